// round 9
// baseline (speedup 1.0000x reference)
#include <cuda_runtime.h>
#include <cstdint>

// ---------------------------------------------------------------------------
// SRNN forward:
//   inp_cur[t,b,r] = sum_i x[b,i,t] * w_inp[r,i]
//   per step t=0..998:
//     v1 = ALPHA*v + z @ w_rec_eff.T + inp_cur[t] - z*THR   (w_rec diag zeroed)
//     z1 = (v1 > THR);  vo1 = KAPPA*vo + z1 @ w_out.T
//   out[0]=0, out[t+1]=vo1.  out shape (1000,128,32) f32
// ---------------------------------------------------------------------------

#define N_B      128
#define INP_DIM  256
#define N_T      1000
#define N_REC    512
#define OUT_DIM  32
#define N_STEPS  999

#define ALPHA 0.9512294245007140f
#define KAPPA 0.9512294245007140f
#define THR   0.6f

#define ROWS  (N_STEPS * N_B)      // 127872 = 864 * 148
#define ROWS_PER_CTA 864

#define WSTEPS 16
#define NWIN   63                  // ceil(999/16); last window has 7 steps
#define NPT    16                  // neurons per thread in k_scan (1 warp/batch)

// ---- scratch (__device__ globals; no allocation) ----
// g_inp padded by one window so the last cp.async window never reads OOB.
__device__ float    g_inp[(size_t)N_B * N_STEPS * N_REC + WSTEPS * N_REC];
__device__ unsigned g_masks[(size_t)ROWS * 8];              // 256-bit mask per (t,b)
__device__ float    g_wrecT[N_REC * N_REC];                 // [s][r], diag 0
__device__ float    g_woutT[N_REC * OUT_DIM];               // [r][o]
__device__ float    g_winpT[INP_DIM * N_REC];               // [i][r]

// ---------------------------------------------------------------------------
// Kernel 1: pack x (b,i,t) into per-(t,b) 256-bit masks. Coalesced over t.
// ---------------------------------------------------------------------------
__global__ void k_masks(const float* __restrict__ x) {
    int b = blockIdx.x;
    int t = blockIdx.y * 256 + threadIdx.x;
    if (t >= N_STEPS) return;

    unsigned m[8] = {0,0,0,0,0,0,0,0};
    const float* xp = x + (size_t)b * INP_DIM * N_T + t;
#pragma unroll
    for (int i = 0; i < INP_DIM; i++) {
        if (xp[(size_t)i * N_T] > 0.5f) m[i >> 5] |= (1u << (i & 31));
    }
    unsigned* dst = g_masks + ((size_t)t * N_B + b) * 8;
#pragma unroll
    for (int w = 0; w < 8; w++) dst[w] = m[w];
}

// ---------------------------------------------------------------------------
// Kernel 2: weight transposes.
// ---------------------------------------------------------------------------
__global__ void k_prep(const float* __restrict__ w_rec,
                       const float* __restrict__ w_out,
                       const float* __restrict__ w_inp) {
    int stride = gridDim.x * blockDim.x;
    int idx0 = blockIdx.x * blockDim.x + threadIdx.x;

    for (int i = idx0; i < N_REC * N_REC; i += stride) {
        int s = i >> 9, r = i & (N_REC - 1);
        float v = w_rec[(size_t)r * N_REC + s];
        g_wrecT[i] = (r == s) ? 0.0f : v;
    }
    for (int i = idx0; i < N_REC * OUT_DIM; i += stride) {
        int r = i >> 5, o = i & 31;
        g_woutT[i] = w_out[(size_t)o * N_REC + r];
    }
    for (int i = idx0; i < INP_DIM * N_REC; i += stride) {
        int ii = i >> 9, r = i & (N_REC - 1);
        g_winpT[i] = w_inp[(size_t)r * INP_DIM + ii];
    }
}

// ---------------------------------------------------------------------------
// Kernel 3: sparse input GEMM — R2 structure, 16 warps (was 8) for latency
// hiding. Warp-per-row, prefetched 32B mask loads, ffs->LDS.128->FADD.
//   grid (4 rec-slices, 148 chunks), 512 threads, 128 KB smem.
// ---------------------------------------------------------------------------
#define K_INP_SMEM (INP_DIM * 128 * 4)

__global__ void __launch_bounds__(512) k_inp_kernel() {
    extern __shared__ float w_sh[];               // [256 i][128 r]

    int slice = blockIdx.x;                       // 0..3
    int chunk = blockIdx.y;                       // 0..147
    int tid   = threadIdx.x;
    int wid   = tid >> 5;                         // 0..15
    int lane  = tid & 31;
    int r0    = slice * 128;

    for (int idx = tid; idx < INP_DIM * 128; idx += 512) {
        int i = idx >> 7, rr = idx & 127;
        w_sh[idx] = g_winpT[(size_t)i * N_REC + r0 + rr];
    }
    __syncthreads();

    int rowbase = chunk * ROWS_PER_CTA;
    int row0 = rowbase + wid;
    unsigned mw = (lane < 8) ? __ldg(&g_masks[(size_t)row0 * 8 + lane]) : 0u;

    for (int j = 0; j < ROWS_PER_CTA / 16; j++) {            // 54 rows/warp
        int row = rowbase + j * 16 + wid;
        unsigned curw = mw;
        if (j < ROWS_PER_CTA / 16 - 1)
            mw = (lane < 8) ? __ldg(&g_masks[(size_t)(row + 16) * 8 + lane]) : 0u;

        float4 acc = make_float4(0.f, 0.f, 0.f, 0.f);
#pragma unroll
        for (int w = 0; w < 8; w++) {
            unsigned m = __shfl_sync(0xffffffffu, curw, w);
            int ibase = w * 32;
            while (m) {
                int i = ibase + __ffs((int)m) - 1;
                m &= (m - 1);
                float4 wv = *(const float4*)&w_sh[(i << 7) + (lane << 2)];
                acc.x += wv.x; acc.y += wv.y; acc.z += wv.z; acc.w += wv.w;
            }
        }
        int t = row >> 7, bb = row & 127;         // row = t*128 + b
        float4* dst = (float4*)(g_inp + ((size_t)bb * N_STEPS + t) * N_REC + r0) + lane;
        *dst = acc;
    }
}

// ---------------------------------------------------------------------------
// Kernel 4: ONE-WARP-PER-BATCH scan. 32 threads, 16 neurons/thread
// (neuron = lane*16 + j, contiguous per thread -> 4x LDS.128 per step).
// Spike exchange via __any_sync/__shfl_sync — ZERO block barriers.
// Input streamed through cp.async double-buffered smem windows.
// ---------------------------------------------------------------------------
#define K_SCAN_SMEM (2 * WSTEPS * N_REC * 4)     // 65536 bytes

__global__ void __launch_bounds__(32) k_scan(float* __restrict__ out) {
    extern __shared__ float sbuf[];              // 2 x WSTEPS*N_REC

    int b    = blockIdx.x;
    int lane = threadIdx.x;                      // 0..31

    const float* gbase = g_inp + (size_t)b * N_STEPS * N_REC;

    // one window = 32 KB; 32 threads x 64 x 16B cp.async
    auto issue_copy = [&](int w, int buf) {
        const float* src = gbase + (size_t)w * WSTEPS * N_REC;
        float* dstb = &sbuf[buf * (WSTEPS * N_REC)];
#pragma unroll
        for (int j = 0; j < 64; j++) {
            unsigned dst = (unsigned)__cvta_generic_to_shared(
                dstb + (j * 32 + lane) * 4);
            asm volatile("cp.async.cg.shared.global [%0], [%1], 16;" ::
                         "r"(dst), "l"(src + (j * 32 + lane) * 4) : "memory");
        }
        asm volatile("cp.async.commit_group;" ::: "memory");
    };

    out[b * OUT_DIM + lane] = 0.f;               // out[0] = 0 (lane == o)

    issue_copy(0, 0);
    issue_copy(1, 1);

    float v[NPT], zf[NPT];
#pragma unroll
    for (int j = 0; j < NPT; j++) { v[j] = 0.f; zf[j] = 0.f; }
    float vo = 0.f;
    unsigned prev_bits = 0;                      // my neurons' spikes last step
    int any_prev = 0;

    for (int w = 0; w < NWIN; w++) {
        int t0 = w * WSTEPS;
        int C = N_STEPS - t0; if (C > WSTEPS) C = WSTEPS;

        asm volatile("cp.async.wait_group 1;" ::: "memory");
        __syncwarp();
        const float* sb = sbuf + (w & 1) * (WSTEPS * N_REC) + lane * NPT;

        for (int c = 0; c < C; c++) {
            // recurrent currents from last step's spikes (rare)
            float racc[NPT];
#pragma unroll
            for (int j = 0; j < NPT; j++) racc[j] = 0.f;
            if (any_prev) {
#pragma unroll 4
                for (int L = 0; L < 32; L++) {
                    unsigned m = __shfl_sync(0xffffffffu, prev_bits, L);
                    while (m) {
                        int jj = __ffs((int)m) - 1;
                        m &= (m - 1);
                        int s = L * NPT + jj;
                        const float4* wr =
                            (const float4*)(g_wrecT + ((size_t)s << 9) + lane * NPT);
#pragma unroll
                        for (int q = 0; q < 4; q++) {
                            float4 wv = __ldg(wr + q);
                            racc[q * 4 + 0] += wv.x; racc[q * 4 + 1] += wv.y;
                            racc[q * 4 + 2] += wv.z; racc[q * 4 + 3] += wv.w;
                        }
                    }
                }
            }

            // membrane update, 16 contiguous neurons
            const float4* in4 = (const float4*)(sb + c * N_REC);
            unsigned bits = 0;
#pragma unroll
            for (int q = 0; q < 4; q++) {
                float4 iv = in4[q];
                float in_[4] = { iv.x, iv.y, iv.z, iv.w };
#pragma unroll
                for (int k = 0; k < 4; k++) {
                    int j = q * 4 + k;
                    float vn = fmaf(ALPHA, v[j], in_[k] + racc[j]) - zf[j] * THR;
                    int z = vn > THR;
                    v[j] = vn;
                    zf[j] = z ? 1.f : 0.f;
                    if (z) bits |= (1u << j);
                }
            }

            int any = __any_sync(0xffffffffu, bits != 0);

            // output layer: every lane owns one of the 32 outputs
            vo = KAPPA * vo;
            if (any) {
#pragma unroll 4
                for (int L = 0; L < 32; L++) {
                    unsigned m = __shfl_sync(0xffffffffu, bits, L);
                    while (m) {
                        int jj = __ffs((int)m) - 1;
                        m &= (m - 1);
                        int s = L * NPT + jj;
                        vo += g_woutT[(s << 5) + lane];
                    }
                }
            }
            out[(size_t)(t0 + c + 1) * (N_B * OUT_DIM) + b * OUT_DIM + lane] = vo;

            prev_bits = bits;
            any_prev = any;
        }

        __syncwarp();
        int wn = w + 2; if (wn > NWIN - 1) wn = NWIN - 1;   // clamp; pad covers tail
        issue_copy(wn, w & 1);
    }
    asm volatile("cp.async.wait_all;" ::: "memory");
}

// ---------------------------------------------------------------------------
extern "C" void kernel_launch(void* const* d_in, const int* in_sizes, int n_in,
                              void* d_out, int out_size) {
    const float* x     = (const float*)d_in[0];
    const float* w_inp = (const float*)d_in[1];
    const float* w_rec = (const float*)d_in[2];
    const float* w_out = (const float*)d_in[3];
    float* out = (float*)d_out;

    cudaFuncSetAttribute(k_inp_kernel,
                         cudaFuncAttributeMaxDynamicSharedMemorySize, K_INP_SMEM);
    cudaFuncSetAttribute(k_scan,
                         cudaFuncAttributeMaxDynamicSharedMemorySize, K_SCAN_SMEM);

    k_masks<<<dim3(N_B, 4), 256>>>(x);
    k_prep<<<256, 256>>>(w_rec, w_out, w_inp);
    k_inp_kernel<<<dim3(4, 148), 512, K_INP_SMEM>>>();
    k_scan<<<N_B, 32, K_SCAN_SMEM>>>(out);
}